// round 1
// baseline (speedup 1.0000x reference)
#include <cuda_runtime.h>
#include <math.h>

// MatchNet: per-sample MLP (6->20->20->20->8 tanh) + 150-iter PDHG QP solve.
// One thread per sample; all QP state in registers; S constant-folded.

__global__ void __launch_bounds__(128, 1) matchnet_kernel(
    const float* __restrict__ X,
    const float* __restrict__ W1, const float* __restrict__ b1,
    const float* __restrict__ W2, const float* __restrict__ b2,
    const float* __restrict__ W3, const float* __restrict__ b3,
    const float* __restrict__ W4, const float* __restrict__ b4,
    float* __restrict__ out, int B)
{
    __shared__ __align__(16) float sW1[120];
    __shared__ __align__(16) float sW2[400];
    __shared__ __align__(16) float sW3[400];
    __shared__ __align__(16) float sW4[160];
    __shared__ float sb1[20], sb2[20], sb3[20], sb4[8];

    const int t = threadIdx.x;
    for (int i = t; i < 120; i += 128) sW1[i] = W1[i];
    for (int i = t; i < 400; i += 128) sW2[i] = W2[i];
    for (int i = t; i < 400; i += 128) sW3[i] = W3[i];
    for (int i = t; i < 160; i += 128) sW4[i] = W4[i];
    if (t < 20) { sb1[t] = b1[t]; sb2[t] = b2[t]; sb3[t] = b3[t]; }
    if (t < 8)  { sb4[t] = b4[t]; }
    __syncthreads();

    const int idx = blockIdx.x * 128 + t;
    if (idx >= B) return;

    // ---- load bids Z (6 floats, also the QP rhs b) ----
    float Z[6];
    {
        const float2* Xp = reinterpret_cast<const float2*>(X + (size_t)idx * 6);
        float2 a0 = Xp[0], a1 = Xp[1], a2 = Xp[2];
        Z[0] = a0.x; Z[1] = a0.y; Z[2] = a1.x; Z[3] = a1.y; Z[4] = a2.x; Z[5] = a2.y;
    }

    // ---- MLP ----
    float h1[20], h2[20];
#pragma unroll
    for (int o = 0; o < 20; ++o) {
        const float2* w = reinterpret_cast<const float2*>(&sW1[o * 6]);
        float2 w0 = w[0], w1 = w[1], w2 = w[2];
        float a = sb1[o];
        a = fmaf(w0.x, Z[0], a); a = fmaf(w0.y, Z[1], a);
        a = fmaf(w1.x, Z[2], a); a = fmaf(w1.y, Z[3], a);
        a = fmaf(w2.x, Z[4], a); a = fmaf(w2.y, Z[5], a);
        h1[o] = tanhf(a);
    }
#pragma unroll
    for (int o = 0; o < 20; ++o) {
        const float4* w = reinterpret_cast<const float4*>(&sW2[o * 20]);
        float a = sb2[o];
#pragma unroll
        for (int q = 0; q < 5; ++q) {
            float4 wq = w[q];
            a = fmaf(wq.x, h1[q * 4 + 0], a);
            a = fmaf(wq.y, h1[q * 4 + 1], a);
            a = fmaf(wq.z, h1[q * 4 + 2], a);
            a = fmaf(wq.w, h1[q * 4 + 3], a);
        }
        h2[o] = tanhf(a);
    }
#pragma unroll
    for (int o = 0; o < 20; ++o) {
        const float4* w = reinterpret_cast<const float4*>(&sW3[o * 20]);
        float a = sb3[o];
#pragma unroll
        for (int q = 0; q < 5; ++q) {
            float4 wq = w[q];
            a = fmaf(wq.x, h2[q * 4 + 0], a);
            a = fmaf(wq.y, h2[q * 4 + 1], a);
            a = fmaf(wq.z, h2[q * 4 + 2], a);
            a = fmaf(wq.w, h2[q * 4 + 3], a);
        }
        h1[o] = tanhf(a);  // reuse h1 as layer-3 output
    }
    float z[8];
#pragma unroll
    for (int o = 0; o < 8; ++o) {
        const float4* w = reinterpret_cast<const float4*>(&sW4[o * 20]);
        float a = sb4[o];
#pragma unroll
        for (int q = 0; q < 5; ++q) {
            float4 wq = w[q];
            a = fmaf(wq.x, h1[q * 4 + 0], a);
            a = fmaf(wq.y, h1[q * 4 + 1], a);
            a = fmaf(wq.z, h1[q * 4 + 2], a);
            a = fmaf(wq.w, h1[q * 4 + 3], a);
        }
        z[o] = tanhf(a);
    }

    // ---- PDHG QP: max w.x - ||x - z||  s.t. x >= 0, S x <= Z,  w = 1 ----
    const float tau = 0.9f / sqrtf(26.0f);  // sigma == tau; L = sqrt(sum(S*S)+8) = sqrt(26)

    float x[8], l2v[8], cz[8];
#pragma unroll
    for (int j = 0; j < 8; ++j) {
        x[j]   = fmaxf(z[j], 0.0f);
        l2v[j] = 0.0f;
        cz[j]  = tau - z[j];   // (tau*w - z), loop-invariant
    }
    float l1v[6], sbb[6];
#pragma unroll
    for (int i = 0; i < 6; ++i) { l1v[i] = 0.0f; sbb[i] = tau * Z[i]; }  // sigma*b

#pragma unroll 1
    for (int it = 0; it < 150; ++it) {
        // s = S^T l1. Columns of S: 0:{0,3} 1:{1,4} 2:{2,5} 3:{0,1,5} 4:{2,3,5} 5:{0,3} 6:{1,4} 7:{2,4}
        float s0 = l1v[0] + l1v[3];
        float s1 = l1v[1] + l1v[4];
        float s2 = l1v[2] + l1v[5];
        float s3 = (l1v[0] + l1v[1]) + l1v[5];
        float s4 = (l1v[2] + l1v[3]) + l1v[5];
        float s7 = l1v[2] + l1v[4];
        float sv[8] = { s0, s1, s2, s3, s4, s0, s1, s7 };

        // v = (x - tau*(s - l2)) + tau*w - z
        float v[8];
#pragma unroll
        for (int j = 0; j < 8; ++j) {
            float a = x[j] + cz[j];
            a = fmaf(tau, l2v[j], a);
            v[j] = fmaf(-tau, sv[j], a);
        }

        // ||v||^2 (two chains of 4 for latency balance)
        float c0 = v[0] * v[0];
        c0 = fmaf(v[1], v[1], c0);
        c0 = fmaf(v[2], v[2], c0);
        c0 = fmaf(v[3], v[3], c0);
        float c1 = v[4] * v[4];
        c1 = fmaf(v[5], v[5], c1);
        c1 = fmaf(v[6], v[6], c1);
        c1 = fmaf(v[7], v[7], c1);
        float ss = c0 + c1;

        // scale = max(1 - tau/||v||, 0); rsqrt(0)=inf -> clamps to 0 like the reference guard
        float r = rsqrtf(ss);
        float scale = fmaxf(fmaf(-tau, r, 1.0f), 0.0f);

        // x_new = z + scale*v ; xbar = 2*x_new - x
        float xb[8];
#pragma unroll
        for (int j = 0; j < 8; ++j) {
            float xn = fmaf(scale, v[j], z[j]);
            xb[j] = fmaf(2.0f, xn, -x[j]);
            x[j] = xn;
        }

        // Sxb rows: 0:{0,3,5} 1:{1,3,6} 2:{2,4,7} 3:{0,4,5} 4:{1,6,7} 5:{2,3,4}
        float p05 = xb[0] + xb[5];
        float p16 = xb[1] + xb[6];
        float p24 = xb[2] + xb[4];
        float rr[6];
        rr[0] = p05 + xb[3];
        rr[1] = p16 + xb[3];
        rr[2] = p24 + xb[7];
        rr[3] = p05 + xb[4];
        rr[4] = p16 + xb[7];
        rr[5] = p24 + xb[3];

        // dual updates
#pragma unroll
        for (int i = 0; i < 6; ++i)
            l1v[i] = fmaxf(fmaf(tau, rr[i], l1v[i]) - sbb[i], 0.0f);
#pragma unroll
        for (int j = 0; j < 8; ++j)
            l2v[j] = fmaxf(fmaf(-tau, xb[j], l2v[j]), 0.0f);
    }

    float4* op = reinterpret_cast<float4*>(out + (size_t)idx * 8);
    op[0] = make_float4(x[0], x[1], x[2], x[3]);
    op[1] = make_float4(x[4], x[5], x[6], x[7]);
}

extern "C" void kernel_launch(void* const* d_in, const int* in_sizes, int n_in,
                              void* d_out, int out_size)
{
    // metadata order: X, W1, b1, W2, b2, W3, b3, W4, b4, S, batch_size
    const float* X  = (const float*)d_in[0];
    const float* W1 = (const float*)d_in[1];
    const float* b1 = (const float*)d_in[2];
    const float* W2 = (const float*)d_in[3];
    const float* b2 = (const float*)d_in[4];
    const float* W3 = (const float*)d_in[5];
    const float* b3 = (const float*)d_in[6];
    const float* W4 = (const float*)d_in[7];
    const float* b4 = (const float*)d_in[8];
    // d_in[9] = S (constant-folded), d_in[10] = batch_size (derived from sizes)

    const int B = in_sizes[0] / 6;
    float* out = (float*)d_out;

    const int block = 128;
    const int grid = (B + block - 1) / block;
    matchnet_kernel<<<grid, block>>>(X, W1, b1, W2, b2, W3, b3, W4, b4, out, B);
}

// round 2
// speedup vs baseline: 1.1312x; 1.1312x over previous
#include <cuda_runtime.h>
#include <math.h>

typedef unsigned long long u64;

__device__ __forceinline__ u64 f2pk(float lo, float hi) {
    u64 r; asm("mov.b64 %0,{%1,%2};" : "=l"(r) : "f"(lo), "f"(hi)); return r;
}
__device__ __forceinline__ void f2upk(u64 a, float& lo, float& hi) {
    asm("mov.b64 {%0,%1},%2;" : "=f"(lo), "=f"(hi) : "l"(a));
}
__device__ __forceinline__ u64 f2add(u64 a, u64 b) {
    u64 d; asm("add.rn.f32x2 %0,%1,%2;" : "=l"(d) : "l"(a), "l"(b)); return d;
}
__device__ __forceinline__ u64 f2mul(u64 a, u64 b) {
    u64 d; asm("mul.rn.f32x2 %0,%1,%2;" : "=l"(d) : "l"(a), "l"(b)); return d;
}
__device__ __forceinline__ u64 f2fma(u64 a, u64 b, u64 c) {
    u64 d; asm("fma.rn.f32x2 %0,%1,%2,%3;" : "=l"(d) : "l"(a), "l"(b), "l"(c)); return d;
}

__global__ void __launch_bounds__(128, 1) matchnet_kernel(
    const float* __restrict__ X,
    const float* __restrict__ W1, const float* __restrict__ b1,
    const float* __restrict__ W2, const float* __restrict__ b2,
    const float* __restrict__ W3, const float* __restrict__ b3,
    const float* __restrict__ W4, const float* __restrict__ b4,
    float* __restrict__ out, int B)
{
    __shared__ __align__(16) float sW1[120];
    __shared__ __align__(16) float sW2[400];
    __shared__ __align__(16) float sW3[400];
    __shared__ __align__(16) float sW4[160];
    __shared__ float sb1[20], sb2[20], sb3[20], sb4[8];

    const int t = threadIdx.x;
    for (int i = t; i < 120; i += 128) sW1[i] = W1[i];
    for (int i = t; i < 400; i += 128) sW2[i] = W2[i];
    for (int i = t; i < 400; i += 128) sW3[i] = W3[i];
    for (int i = t; i < 160; i += 128) sW4[i] = W4[i];
    if (t < 20) { sb1[t] = b1[t]; sb2[t] = b2[t]; sb3[t] = b3[t]; }
    if (t < 8)  { sb4[t] = b4[t]; }
    __syncthreads();

    const int idx = blockIdx.x * 128 + t;
    if (idx >= B) return;

    // ---- load bids Z (6 floats, also the QP rhs b) ----
    float Z[6];
    {
        const float2* Xp = reinterpret_cast<const float2*>(X + (size_t)idx * 6);
        float2 a0 = Xp[0], a1 = Xp[1], a2 = Xp[2];
        Z[0] = a0.x; Z[1] = a0.y; Z[2] = a1.x; Z[3] = a1.y; Z[4] = a2.x; Z[5] = a2.y;
    }

    // ---- MLP 6->20->20->20->8, tanh ----
    float h1[20], h2[20];
#pragma unroll
    for (int o = 0; o < 20; ++o) {
        const float2* w = reinterpret_cast<const float2*>(&sW1[o * 6]);
        float2 w0 = w[0], w1 = w[1], w2 = w[2];
        float a = sb1[o];
        a = fmaf(w0.x, Z[0], a); a = fmaf(w0.y, Z[1], a);
        a = fmaf(w1.x, Z[2], a); a = fmaf(w1.y, Z[3], a);
        a = fmaf(w2.x, Z[4], a); a = fmaf(w2.y, Z[5], a);
        h1[o] = tanhf(a);
    }
#pragma unroll
    for (int o = 0; o < 20; ++o) {
        const float4* w = reinterpret_cast<const float4*>(&sW2[o * 20]);
        float a = sb2[o];
#pragma unroll
        for (int q = 0; q < 5; ++q) {
            float4 wq = w[q];
            a = fmaf(wq.x, h1[q * 4 + 0], a);
            a = fmaf(wq.y, h1[q * 4 + 1], a);
            a = fmaf(wq.z, h1[q * 4 + 2], a);
            a = fmaf(wq.w, h1[q * 4 + 3], a);
        }
        h2[o] = tanhf(a);
    }
#pragma unroll
    for (int o = 0; o < 20; ++o) {
        const float4* w = reinterpret_cast<const float4*>(&sW3[o * 20]);
        float a = sb3[o];
#pragma unroll
        for (int q = 0; q < 5; ++q) {
            float4 wq = w[q];
            a = fmaf(wq.x, h2[q * 4 + 0], a);
            a = fmaf(wq.y, h2[q * 4 + 1], a);
            a = fmaf(wq.z, h2[q * 4 + 2], a);
            a = fmaf(wq.w, h2[q * 4 + 3], a);
        }
        h1[o] = tanhf(a);
    }
    float z[8];
#pragma unroll
    for (int o = 0; o < 8; ++o) {
        const float4* w = reinterpret_cast<const float4*>(&sW4[o * 20]);
        float a = sb4[o];
#pragma unroll
        for (int q = 0; q < 5; ++q) {
            float4 wq = w[q];
            a = fmaf(wq.x, h1[q * 4 + 0], a);
            a = fmaf(wq.y, h1[q * 4 + 1], a);
            a = fmaf(wq.z, h1[q * 4 + 2], a);
            a = fmaf(wq.w, h1[q * 4 + 3], a);
        }
        z[o] = tanhf(a);
    }

    // ---- PDHG QP (packed f32x2), state scaled by tau:
    //   L2' = tau*l2 (>=0, packed), m = -tau*l1 (<=0, scalar)
    const float tau  = 0.9f / sqrtf(26.0f);
    const float tau2 = tau * tau;

    const u64 NEG1 = 0xBF800000BF800000ULL;           // (-1, -1)
    const u64 NT2  = f2pk(-tau2, -tau2);

    // packed constants
    u64 zp[4], czp[4];
#pragma unroll
    for (int k = 0; k < 4; ++k) {
        zp[k]  = f2pk(z[2 * k], z[2 * k + 1]);
        czp[k] = f2pk(tau - z[2 * k], tau - z[2 * k + 1]);
    }
    u64 sb2p[3];
    sb2p[0] = f2pk(tau2 * Z[0], tau2 * Z[1]);
    sb2p[1] = f2pk(tau2 * Z[2], tau2 * Z[3]);
    sb2p[2] = f2pk(tau2 * Z[4], tau2 * Z[5]);

    // state
    u64 xp[4], l2p[4];
#pragma unroll
    for (int k = 0; k < 4; ++k) {
        xp[k]  = f2pk(fmaxf(z[2 * k], 0.0f), fmaxf(z[2 * k + 1], 0.0f));
        l2p[k] = 0ULL;
    }
    float m0 = 0.f, m1 = 0.f, m2 = 0.f, m3 = 0.f, m4 = 0.f, m5 = 0.f;

#pragma unroll 1
    for (int it = 0; it < 150; ++it) {
        // sv'' = -tau * S^T l1 (sums of m, all <= 0), packed pairs
        // cols: 0:{0,3} 1:{1,4} 2:{2,5} 3:{0,1,5} 4:{2,3,5} 5:{0,3} 6:{1,4} 7:{2,4}
        u64 s01 = f2add(f2pk(m0, m1), f2pk(m3, m4));       // (sv0, sv1)
        float t01 = m0 + m1;
        u64 s23 = f2add(f2pk(m2, t01), f2pk(m5, m5));      // (sv2, sv3)
        float t23 = m2 + m3;
        float sv4 = t23 + m5;
        float sv0, sv1; f2upk(s01, sv0, sv1);
        u64 s45 = f2pk(sv4, sv0);                          // (sv4, sv5=sv0)
        u64 s67 = f2add(f2pk(m1, m2), f2pk(m4, m4));       // (sv6=sv1, sv7)

        // v = (x + cz) + (L2' + sv'')
        u64 v0 = f2add(f2add(xp[0], czp[0]), f2add(l2p[0], s01));
        u64 v1 = f2add(f2add(xp[1], czp[1]), f2add(l2p[1], s23));
        u64 v2 = f2add(f2add(xp[2], czp[2]), f2add(l2p[2], s45));
        u64 v3 = f2add(f2add(xp[3], czp[3]), f2add(l2p[3], s67));

        // ||v||^2
        u64 nm = f2mul(v0, v0);
        nm = f2fma(v1, v1, nm);
        nm = f2fma(v2, v2, nm);
        nm = f2fma(v3, v3, nm);
        float na, nb; f2upk(nm, na, nb);
        float ss = na + nb;

        // scale = max(1 - tau/||v||, 0); rsqrt(0)=inf -> clamps to 0
        float r = rsqrtf(ss);
        float scale = fmaxf(fmaf(-tau, r, 1.0f), 0.0f);
        u64 sc2 = f2pk(scale, scale);

        // xn = z + scale*v ; xb = 2*xn - x = xn + (xn - x)
        u64 xn0 = f2fma(v0, sc2, zp[0]);
        u64 xn1 = f2fma(v1, sc2, zp[1]);
        u64 xn2 = f2fma(v2, sc2, zp[2]);
        u64 xn3 = f2fma(v3, sc2, zp[3]);
        u64 xb0 = f2add(xn0, f2fma(xp[0], NEG1, xn0));
        u64 xb1 = f2add(xn1, f2fma(xp[1], NEG1, xn1));
        u64 xb2 = f2add(xn2, f2fma(xp[2], NEG1, xn2));
        u64 xb3 = f2add(xn3, f2fma(xp[3], NEG1, xn3));
        xp[0] = xn0; xp[1] = xn1; xp[2] = xn2; xp[3] = xn3;

        float e0, e1, e2, e3, e4, e5, e6, e7;
        f2upk(xb0, e0, e1); f2upk(xb1, e2, e3);
        f2upk(xb2, e4, e5); f2upk(xb3, e6, e7);

        // rr = S @ xb, rows: 0:{0,3,5} 1:{1,3,6} 2:{2,4,7} 3:{0,4,5} 4:{1,6,7} 5:{2,3,4}
        u64 pp = f2add(xb0, f2pk(e5, e6));                 // (p05, p16)
        float p05, p16; f2upk(pp, p05, p16);
        float p24 = e2 + e4;
        u64 rr01 = f2add(pp, f2pk(e3, e3));                // (rr0, rr1)
        u64 rr23 = f2add(f2pk(p24, p05), f2pk(e7, e4));    // (rr2, rr3)
        u64 rr45 = f2add(f2pk(p16, p24), f2pk(e7, e3));    // (rr4, rr5)

        // l1 dual (negated, scaled): m = min(m - tau2*rr + tau2*b, 0)
        u64 u01 = f2add(f2fma(rr01, NT2, f2pk(m0, m1)), sb2p[0]);
        u64 u23 = f2add(f2fma(rr23, NT2, f2pk(m2, m3)), sb2p[1]);
        u64 u45 = f2add(f2fma(rr45, NT2, f2pk(m4, m5)), sb2p[2]);
        float q0, q1, q2, q3, q4, q5;
        f2upk(u01, q0, q1); f2upk(u23, q2, q3); f2upk(u45, q4, q5);
        m0 = fminf(q0, 0.0f); m1 = fminf(q1, 0.0f); m2 = fminf(q2, 0.0f);
        m3 = fminf(q3, 0.0f); m4 = fminf(q4, 0.0f); m5 = fminf(q5, 0.0f);

        // l2 dual (scaled): L2' = max(L2' - tau2*xb, 0)
#pragma unroll
        for (int k = 0; k < 4; ++k) {
            u64 w = f2fma((k == 0 ? xb0 : k == 1 ? xb1 : k == 2 ? xb2 : xb3), NT2, l2p[k]);
            float a, b2v; f2upk(w, a, b2v);
            l2p[k] = f2pk(fmaxf(a, 0.0f), fmaxf(b2v, 0.0f));
        }
    }

    float o0, o1, o2, o3, o4, o5, o6, o7;
    f2upk(xp[0], o0, o1); f2upk(xp[1], o2, o3);
    f2upk(xp[2], o4, o5); f2upk(xp[3], o6, o7);
    float4* op = reinterpret_cast<float4*>(out + (size_t)idx * 8);
    op[0] = make_float4(o0, o1, o2, o3);
    op[1] = make_float4(o4, o5, o6, o7);
}

extern "C" void kernel_launch(void* const* d_in, const int* in_sizes, int n_in,
                              void* d_out, int out_size)
{
    const float* X  = (const float*)d_in[0];
    const float* W1 = (const float*)d_in[1];
    const float* b1 = (const float*)d_in[2];
    const float* W2 = (const float*)d_in[3];
    const float* b2 = (const float*)d_in[4];
    const float* W3 = (const float*)d_in[5];
    const float* b3 = (const float*)d_in[6];
    const float* W4 = (const float*)d_in[7];
    const float* b4 = (const float*)d_in[8];

    const int B = in_sizes[0] / 6;
    float* out = (float*)d_out;

    const int block = 128;
    const int grid = (B + block - 1) / block;
    matchnet_kernel<<<grid, block>>>(X, W1, b1, W2, b2, W3, b3, W4, b4, out, B);
}